// round 5
// baseline (speedup 1.0000x reference)
#include <cuda_runtime.h>
#include <cstddef>
#include <cstdint>

#define C_DIM 64
#define H_DIM 150000
#define K_DIM 27
#define TILE_H 64
#define NBLK_H ((H_DIM + TILE_H - 1) / TILE_H)   // 2344

// Scratch: node-major x (x_t[h][c]), k-major neigh (nt[k][h]), zero row.
__device__ float g_xt[(size_t)H_DIM * C_DIM];   // 38.4 MB
__device__ int   g_nt[(size_t)K_DIM * H_DIM];   // 16.2 MB
__device__ float g_zero[C_DIM];                 // 256 B, zero-initialized

// ---------------------------------------------------------------------------
// Transpose x: (C, H) -> (H, C). 32h x 32c tile, block (32,8).
// ---------------------------------------------------------------------------
__global__ __launch_bounds__(256) void transpose_x_kernel(const float* __restrict__ x) {
    __shared__ float tile[32][33];
    const int hb = blockIdx.x * 32;
    const int cb = blockIdx.y * 32;
    const int tx = threadIdx.x, ty = threadIdx.y;

    const int h = hb + tx;
    if (h < H_DIM) {
        #pragma unroll
        for (int i = 0; i < 4; ++i) {
            const int c = cb + ty * 4 + i;
            tile[ty * 4 + i][tx] = x[(size_t)c * H_DIM + h];
        }
    }
    __syncthreads();

    const int j   = ty * 32 + tx;
    const int row = j / 8;
    const int cg  = j % 8;
    const int hh  = hb + row;
    if (hh < H_DIM) {
        float4 v = make_float4(tile[cg * 4 + 0][row], tile[cg * 4 + 1][row],
                               tile[cg * 4 + 2][row], tile[cg * 4 + 3][row]);
        *reinterpret_cast<float4*>(&g_xt[(size_t)hh * C_DIM + cb + cg * 4]) = v;
    }
}

// ---------------------------------------------------------------------------
// Transpose neigh: (H, K) -> (K, H).
// ---------------------------------------------------------------------------
__global__ void transpose_n_kernel(const int* __restrict__ nb) {
    __shared__ int tile[32][33];
    const int hb = blockIdx.x * 32;
    const int tx = threadIdx.x, ty = threadIdx.y;

    const int h_in = hb + ty;
    if (h_in < H_DIM && tx < K_DIM)
        tile[ty][tx] = nb[(size_t)h_in * K_DIM + tx];
    __syncthreads();

    const int h_out = hb + tx;
    if (h_out < H_DIM && ty < K_DIM)
        g_nt[(size_t)ty * H_DIM + h_out] = tile[tx][ty];
}

// ---------------------------------------------------------------------------
// Gather, staged through smem with WORD-level rotation (conflict-free).
// Block = 64 nodes x 64 channels for one k.
//   smem word for (node j, channel c) lives at  j*64 + ((c + j) & 63).
//   Load phase:  warp = 32 consecutive channel words of ONE node
//                -> 1 gmem line per warp-op (cp.async 4B, L1-coalesced),
//                -> STS banks (c+j)&31 distinct: conflict-free.
//   Store phase: warp = 32 consecutive h for one c
//                -> LDS banks (c+h)&31 distinct: conflict-free,
//                -> STG.32 fully coalesced (1 line/warp), __stcs.
// ---------------------------------------------------------------------------
__global__ __launch_bounds__(256) void gather_kernel(float* __restrict__ out) {
    __shared__ float sm[TILE_H * C_DIM];   // 16 KB
    __shared__ int   nidx[TILE_H];

    const int t  = threadIdx.x;
    const int k  = blockIdx.y;
    const int hb = blockIdx.x * TILE_H;

    if (t < TILE_H) {
        const int h = hb + t;
        nidx[t] = (h < H_DIM) ? g_nt[(size_t)k * H_DIM + h] : -1;
    }
    __syncthreads();

    uint32_t sm_base;
    asm volatile("{ .reg .u64 t64; cvta.to.shared.u64 t64, %1; cvt.u32.u64 %0, t64; }"
                 : "=r"(sm_base) : "l"((void*)sm));

    // ---- load phase: 4096 words, 16 rounds of cp.async 4B ----
    #pragma unroll
    for (int r = 0; r < 16; ++r) {
        const int id = r * 256 + t;
        const int j  = id >> 6;          // node within tile (0..63)
        const int c  = id & 63;          // channel word
        const int node = nidx[j];
        const float* src = (node >= 0 ? g_xt + (size_t)node * C_DIM : g_zero) + c;
        const uint32_t dst = sm_base + (uint32_t)((j * C_DIM + ((c + j) & 63)) << 2);
        asm volatile("cp.async.ca.shared.global [%0], [%1], 4;" :: "r"(dst), "l"(src));
    }
    asm volatile("cp.async.commit_group;");
    asm volatile("cp.async.wait_group 0;");
    __syncthreads();

    // ---- store phase: 4096 floats, 16 rounds ----
    const size_t KH = (size_t)K_DIM * H_DIM;
    #pragma unroll
    for (int r = 0; r < 16; ++r) {
        const int id = r * 256 + t;
        const int c  = id >> 6;          // channel (0..63 over rounds)
        const int h  = id & 63;          // node within tile
        const float val = sm[h * C_DIM + ((c + h) & 63)];
        const int hh = hb + h;
        if (hh < H_DIM)
            __stcs(&out[(size_t)c * KH + (size_t)k * H_DIM + hh], val);
    }
}

extern "C" void kernel_launch(void* const* d_in, const int* in_sizes, int n_in,
                              void* d_out, int out_size) {
    const float* x   = (const float*)d_in[0];   // (1, 64, 150000, 1) fp32
    const int*   nb  = (const int*)d_in[1];     // (150000, 27) int32
    float*       out = (float*)d_out;           // (1, 64, 27, 150000) fp32

    (void)in_sizes; (void)n_in; (void)out_size;

    {
        dim3 block(32, 8);
        dim3 grid((H_DIM + 31) / 32, C_DIM / 32);
        transpose_x_kernel<<<grid, block>>>(x);
    }
    {
        dim3 block(32, 32);
        dim3 grid((H_DIM + 31) / 32, 1);
        transpose_n_kernel<<<grid, block>>>(nb);
    }
    {
        dim3 block(256);
        dim3 grid(NBLK_H, K_DIM);
        gather_kernel<<<grid, block>>>(out);
    }
}

// round 6
// speedup vs baseline: 1.9951x; 1.9951x over previous
#include <cuda_runtime.h>
#include <cstddef>
#include <cstdint>

#define C_DIM 64
#define H_DIM 150000
#define K_DIM 27
#define TILE_H 64
#define NBLK_H ((H_DIM + TILE_H - 1) / TILE_H)   // 2344

__device__ float g_xt[(size_t)H_DIM * C_DIM];   // 38.4 MB node-major x
__device__ int   g_nt[(size_t)K_DIM * H_DIM];   // 16.2 MB k-major neigh
__device__ float g_zero[C_DIM];                 // 256 B zeros

// ---------------------------------------------------------------------------
// Transpose x: (C, H) -> (H, C). 32h x 32c tile, block (32,8).
// ---------------------------------------------------------------------------
__global__ __launch_bounds__(256) void transpose_x_kernel(const float* __restrict__ x) {
    __shared__ float tile[32][33];
    const int hb = blockIdx.x * 32;
    const int cb = blockIdx.y * 32;
    const int tx = threadIdx.x, ty = threadIdx.y;

    const int h = hb + tx;
    if (h < H_DIM) {
        #pragma unroll
        for (int i = 0; i < 4; ++i) {
            const int c = cb + ty * 4 + i;
            tile[ty * 4 + i][tx] = x[(size_t)c * H_DIM + h];
        }
    }
    __syncthreads();

    const int j   = ty * 32 + tx;
    const int row = j / 8;
    const int cg  = j % 8;
    const int hh  = hb + row;
    if (hh < H_DIM) {
        float4 v = make_float4(tile[cg * 4 + 0][row], tile[cg * 4 + 1][row],
                               tile[cg * 4 + 2][row], tile[cg * 4 + 3][row]);
        *reinterpret_cast<float4*>(&g_xt[(size_t)hh * C_DIM + cb + cg * 4]) = v;
    }
}

// ---------------------------------------------------------------------------
// Transpose neigh: (H, K) -> (K, H).
// ---------------------------------------------------------------------------
__global__ void transpose_n_kernel(const int* __restrict__ nb) {
    __shared__ int tile[32][33];
    const int hb = blockIdx.x * 32;
    const int tx = threadIdx.x, ty = threadIdx.y;

    const int h_in = hb + ty;
    if (h_in < H_DIM && tx < K_DIM)
        tile[ty][tx] = nb[(size_t)h_in * K_DIM + tx];
    __syncthreads();

    const int h_out = hb + tx;
    if (h_out < H_DIM && ty < K_DIM)
        g_nt[(size_t)ty * H_DIM + h_out] = tile[tx][ty];
}

// ---------------------------------------------------------------------------
// Staged gather. Block = 64 nodes (h) x 64 channels for one k.
// smem: chunk (16B) of (node j, logical chunk q=c>>2) at physical chunk
//       p = (q + (j>>2)) & 15   -> row j, byte offset p*16.
// Load : 16B cp.async.cg; 16 lanes cover one 256B node row (4 lines/warp-op).
//        STS side conflict-free per 128B phase. Masked nodes pull g_zero.
// Store: thread = (c, h4): 4 consecutive h, one c. Warp = 2 c-slices x 64h
//        -> STG.128, 4 lines/warp-op, __stcs. LDS 2-way worst case.
// ---------------------------------------------------------------------------
__global__ __launch_bounds__(256) void gather_kernel(float* __restrict__ out) {
    __shared__ float sm[TILE_H * C_DIM];   // 16 KB
    __shared__ int   nidx[TILE_H];

    const int t  = threadIdx.x;
    const int k  = blockIdx.y;
    const int hb = blockIdx.x * TILE_H;

    if (t < TILE_H) {
        const int h = hb + t;
        nidx[t] = (h < H_DIM) ? g_nt[(size_t)k * H_DIM + h] : -1;
    }
    __syncthreads();

    uint32_t sm_base;
    asm volatile("{ .reg .u64 t64; cvta.to.shared.u64 t64, %1; cvt.u32.u64 %0, t64; }"
                 : "=r"(sm_base) : "l"((void*)sm));

    // ---- load phase: 1024 x cp.async 16B (4 per thread) ----
    #pragma unroll
    for (int r = 0; r < 4; ++r) {
        const int id = r * 256 + t;
        const int j  = id >> 4;              // node in tile (0..63)
        const int q  = id & 15;              // logical 16B chunk
        const int node = nidx[j];
        const float* src = (node >= 0 ? g_xt + (size_t)node * C_DIM : g_zero) + q * 4;
        const int p = (q + (j >> 2)) & 15;   // rotated physical chunk
        const uint32_t dst = sm_base + (uint32_t)((j * C_DIM + p * 4) << 2);
        asm volatile("cp.async.cg.shared.global [%0], [%1], 16;" :: "r"(dst), "l"(src));
    }
    asm volatile("cp.async.commit_group;");
    asm volatile("cp.async.wait_group 0;");
    __syncthreads();

    // ---- store phase: 4 rounds; thread = (c, 4h), STG.128 ----
    const size_t KH = (size_t)K_DIM * H_DIM;
    const bool full = (hb + TILE_H) <= H_DIM;
    #pragma unroll
    for (int r = 0; r < 4; ++r) {
        const int h4 = t & 15;               // group of 4 h (0..15)
        const int c  = (t >> 4) + r * 16;    // channel
        const int q  = c >> 2;
        const int p  = (q + h4) & 15;        // row h: h>>2 == h4
        const int w  = p * 4 + (c & 3);      // word within row
        float4 v;
        v.x = sm[(h4 * 4 + 0) * C_DIM + w];
        v.y = sm[(h4 * 4 + 1) * C_DIM + w];
        v.z = sm[(h4 * 4 + 2) * C_DIM + w];
        v.w = sm[(h4 * 4 + 3) * C_DIM + w];
        const int h = hb + h4 * 4;
        float* dst = &out[(size_t)c * KH + (size_t)k * H_DIM + h];
        if (full) {
            __stcs(reinterpret_cast<float4*>(dst), v);
        } else {
            if (h + 0 < H_DIM) __stcs(dst + 0, v.x);
            if (h + 1 < H_DIM) __stcs(dst + 1, v.y);
            if (h + 2 < H_DIM) __stcs(dst + 2, v.z);
            if (h + 3 < H_DIM) __stcs(dst + 3, v.w);
        }
    }
}

extern "C" void kernel_launch(void* const* d_in, const int* in_sizes, int n_in,
                              void* d_out, int out_size) {
    const float* x   = (const float*)d_in[0];   // (1, 64, 150000, 1) fp32
    const int*   nb  = (const int*)d_in[1];     // (150000, 27) int32
    float*       out = (float*)d_out;           // (1, 64, 27, 150000) fp32

    (void)in_sizes; (void)n_in; (void)out_size;

    {
        dim3 block(32, 8);
        dim3 grid((H_DIM + 31) / 32, C_DIM / 32);
        transpose_x_kernel<<<grid, block>>>(x);
    }
    {
        dim3 block(32, 32);
        dim3 grid((H_DIM + 31) / 32, 1);
        transpose_n_kernel<<<grid, block>>>(nb);
    }
    {
        dim3 block(256);
        dim3 grid(NBLK_H, K_DIM);
        gather_kernel<<<grid, block>>>(out);
    }
}

// round 8
// speedup vs baseline: 2.2888x; 1.1472x over previous
#include <cuda_runtime.h>
#include <cstddef>
#include <cstdint>

#define C_DIM 64
#define H_DIM 150000
#define K_DIM 27
#define TILE_H 64
#define NBLK_H ((H_DIM + TILE_H - 1) / TILE_H)   // 2344

__device__ float g_xt[(size_t)H_DIM * C_DIM];   // 38.4 MB node-major x
__device__ float g_zero[C_DIM];                 // 256 B zeros

// ---------------------------------------------------------------------------
// Transpose x: (C, H) -> (H, C). 32h x 32c tile, block (32,8).
// ---------------------------------------------------------------------------
__global__ __launch_bounds__(256) void transpose_x_kernel(const float* __restrict__ x) {
    __shared__ float tile[32][33];
    const int hb = blockIdx.x * 32;
    const int cb = blockIdx.y * 32;
    const int tx = threadIdx.x, ty = threadIdx.y;

    const int h = hb + tx;
    if (h < H_DIM) {
        #pragma unroll
        for (int i = 0; i < 4; ++i) {
            const int c = cb + ty * 4 + i;
            tile[ty * 4 + i][tx] = x[(size_t)c * H_DIM + h];
        }
    }
    __syncthreads();

    const int j   = ty * 32 + tx;
    const int row = j / 8;
    const int cg  = j % 8;
    const int hh  = hb + row;
    if (hh < H_DIM) {
        float4 v = make_float4(tile[cg * 4 + 0][row], tile[cg * 4 + 1][row],
                               tile[cg * 4 + 2][row], tile[cg * 4 + 3][row]);
        *reinterpret_cast<float4*>(&g_xt[(size_t)hh * C_DIM + cb + cg * 4]) = v;
    }
}

// ---------------------------------------------------------------------------
// Pipelined staged gather. Block = one 64-node h-tile, loops over all 27 k
// with double-buffered cp.async (store of tile k overlaps load of k+1).
//
// smem: 16B chunk of (node j, logical chunk q=c>>2) at physical chunk
//       p = (q + (j>>2)) & 15.
// Load : 16B cp.async.cg, 16 lanes per 256B node row (conflict-free STS).
// Store: thread = (c, 4h) -> STG.128 __stcs; LDS 2-way worst case.
// Index: neigh rows [hb, hb+64) are a contiguous 64*27 int slab -> one
//        coalesced copy, no transpose kernel needed.
// ---------------------------------------------------------------------------
__global__ __launch_bounds__(256) void gather_kernel(const int* __restrict__ neigh,
                                                     float* __restrict__ out) {
    __shared__ float sm[2][TILE_H * C_DIM];       // 2 x 16 KB
    __shared__ int   sidx[TILE_H * K_DIM];        // 6.9 KB

    const int t  = threadIdx.x;
    const int hb = blockIdx.x * TILE_H;
    const int nvalid = (H_DIM - hb < TILE_H) ? (H_DIM - hb) * K_DIM : TILE_H * K_DIM;

    // coalesced copy of the contiguous neigh slab
    #pragma unroll
    for (int r = 0; r < 7; ++r) {
        const int i = r * 256 + t;
        if (i < TILE_H * K_DIM)
            sidx[i] = (i < nvalid) ? neigh[(size_t)hb * K_DIM + i] : -1;
    }
    __syncthreads();

    uint32_t sm_base;
    asm volatile("{ .reg .u64 t64; cvta.to.shared.u64 t64, %1; cvt.u32.u64 %0, t64; }"
                 : "=r"(sm_base) : "l"((void*)sm));

    const int jq = t >> 4;               // node handled in load rounds base
    const int q  = t & 15;               // logical 16B chunk
    const int p  = (q + (jq >> 2)) & 15; // note: same q,j each round offset

    // ---- load issuer for buffer b, neighborhood k ----
    auto issue_load = [&](int k, int b) {
        #pragma unroll
        for (int r = 0; r < 4; ++r) {
            const int j = r * 16 + jq;                 // node in tile (0..63)
            const int node = sidx[j * K_DIM + k];
            const float* src = (node >= 0 ? g_xt + (size_t)node * C_DIM : g_zero) + q * 4;
            const int pp = (q + (j >> 2)) & 15;
            const uint32_t dst = sm_base +
                (uint32_t)(((b * TILE_H + j) * C_DIM + pp * 4) << 2);
            asm volatile("cp.async.cg.shared.global [%0], [%1], 16;" :: "r"(dst), "l"(src));
        }
        asm volatile("cp.async.commit_group;");
    };

    issue_load(0, 0);

    const size_t KH = (size_t)K_DIM * H_DIM;
    const bool full = (hb + TILE_H) <= H_DIM;

    for (int k = 0; k < K_DIM; ++k) {
        if (k + 1 < K_DIM) {
            issue_load(k + 1, (k + 1) & 1);
            asm volatile("cp.async.wait_group 1;");
        } else {
            asm volatile("cp.async.wait_group 0;");
        }
        __syncthreads();

        // store phase for buffer k&1
        const float* buf = sm[k & 1];
        #pragma unroll
        for (int r = 0; r < 4; ++r) {
            const int h4 = t & 15;               // group of 4 h
            const int c  = (t >> 4) + r * 16;    // channel
            const int w  = (((c >> 2) + h4) & 15) * 4 + (c & 3);
            float4 v;
            v.x = buf[(h4 * 4 + 0) * C_DIM + w];
            v.y = buf[(h4 * 4 + 1) * C_DIM + w];
            v.z = buf[(h4 * 4 + 2) * C_DIM + w];
            v.w = buf[(h4 * 4 + 3) * C_DIM + w];
            const int h = hb + h4 * 4;
            float* dst = &out[(size_t)c * KH + (size_t)k * H_DIM + h];
            if (full) {
                __stcs(reinterpret_cast<float4*>(dst), v);
            } else {
                if (h + 0 < H_DIM) __stcs(dst + 0, v.x);
                if (h + 1 < H_DIM) __stcs(dst + 1, v.y);
                if (h + 2 < H_DIM) __stcs(dst + 2, v.z);
                if (h + 3 < H_DIM) __stcs(dst + 3, v.w);
            }
        }
        __syncthreads();   // all reads of buf done before its next overwrite
    }
    (void)p;
}

extern "C" void kernel_launch(void* const* d_in, const int* in_sizes, int n_in,
                              void* d_out, int out_size) {
    const float* x   = (const float*)d_in[0];   // (1, 64, 150000, 1) fp32
    const int*   nb  = (const int*)d_in[1];     // (150000, 27) int32
    float*       out = (float*)d_out;           // (1, 64, 27, 150000) fp32

    (void)in_sizes; (void)n_in; (void)out_size;

    {
        dim3 block(32, 8);
        dim3 grid((H_DIM + 31) / 32, C_DIM / 32);
        transpose_x_kernel<<<grid, block>>>(x);
    }
    {
        dim3 block(256);
        dim3 grid(NBLK_H);
        gather_kernel<<<grid, block>>>(nb, out);
    }
}